// round 1
// baseline (speedup 1.0000x reference)
#include <cuda_runtime.h>

#define NN   50000
#define NE   800000
#define KIN  256
#define MOUT 128
#define NH   4
#define DH   32

// Scratch (allocation-free rule: __device__ globals)
__device__ __align__(16) float g_Wx[NN * MOUT];     // 25.6 MB
__device__ __align__(16) float g_ssrc[NN * NH];     // 0.8 MB
__device__ __align__(16) float g_sdst[NN * NH];     // 0.8 MB
__device__ __align__(16) float g_eexp[NE * NH];     // 12.8 MB
__device__ __align__(16) float g_denom[NN * NH];    // 0.8 MB
__device__ __align__(16) float g_accum[NN * MOUT];  // 25.6 MB

__device__ __forceinline__ void red_add_v4(float* addr, float4 v) {
    asm volatile("red.global.add.v4.f32 [%0], {%1,%2,%3,%4};"
                 :: "l"(addr), "f"(v.x), "f"(v.y), "f"(v.z), "f"(v.w)
                 : "memory");
}

// ---------------------------------------------------------------------------
// Kernel 0: zero accumulators
// ---------------------------------------------------------------------------
__global__ void zero_kernel() {
    int i = blockIdx.x * blockDim.x + threadIdx.x;
    float4 z = make_float4(0.f, 0.f, 0.f, 0.f);
    if (i < NN * MOUT / 4) ((float4*)g_accum)[i] = z;
    if (i < NN * NH / 4)   ((float4*)g_denom)[i] = z;
}

// ---------------------------------------------------------------------------
// Kernel 1: Wx = x @ W^T  (fp32 tiled), fused score epilogue:
//   s_src[n,h] = sum_d Wx[n,h,d]*a_s[d],  s_dst likewise with a_d.
// Block: 256 threads -> 64 rows x 128 cols tile. BK=16.
// Warp layout: tx = lane (col group of 4), ty = warp id (row group of 8).
// A warp's 32 lanes cover all 128 cols of 8 rows -> segmented shfl reduce
// over 8-lane groups gives per-head dot products for free.
// ---------------------------------------------------------------------------
#define BM 64
#define BK 16

__global__ __launch_bounds__(256)
void gemm_score_kernel(const float* __restrict__ x,
                       const float* __restrict__ W,
                       const float* __restrict__ aw) {
    __shared__ float Xs[BK][BM];
    __shared__ float Ws[BK][MOUT];

    int tid = threadIdx.x;
    int tx  = tid & 31;   // lane
    int ty  = tid >> 5;   // warp
    int row0 = blockIdx.x * BM;

    float acc[8][4];
    #pragma unroll
    for (int i = 0; i < 8; i++)
        #pragma unroll
        for (int j = 0; j < 4; j++) acc[i][j] = 0.f;

    for (int k0 = 0; k0 < KIN; k0 += BK) {
        // Load X tile: 64x16 = 256 float4
        {
            int m  = tid >> 2;          // 0..63
            int kv = (tid & 3) * 4;     // 0,4,8,12
            int row = row0 + m;
            float4 v = make_float4(0.f, 0.f, 0.f, 0.f);
            if (row < NN) v = *(const float4*)&x[row * KIN + k0 + kv];
            Xs[kv + 0][m] = v.x; Xs[kv + 1][m] = v.y;
            Xs[kv + 2][m] = v.z; Xs[kv + 3][m] = v.w;
        }
        // Load W tile: 128x16 = 512 float4, 2 per thread
        #pragma unroll
        for (int j = 0; j < 2; j++) {
            int idx = tid * 2 + j;      // 0..511
            int o   = idx >> 2;         // 0..127
            int kv  = (idx & 3) * 4;
            float4 v = *(const float4*)&W[o * KIN + k0 + kv];
            Ws[kv + 0][o] = v.x; Ws[kv + 1][o] = v.y;
            Ws[kv + 2][o] = v.z; Ws[kv + 3][o] = v.w;
        }
        __syncthreads();

        #pragma unroll
        for (int k = 0; k < BK; k++) {
            float4 b = *(float4*)&Ws[k][tx * 4];   // 128-bit LDS, conflict-free
            #pragma unroll
            for (int i = 0; i < 8; i++) {
                float a = Xs[k][ty * 8 + i];       // warp-broadcast
                acc[i][0] += a * b.x; acc[i][1] += a * b.y;
                acc[i][2] += a * b.z; acc[i][3] += a * b.w;
            }
        }
        __syncthreads();
    }

    // Epilogue: store Wx rows + fused attention score reductions
    float4 as4 = *(const float4*)&aw[(tx & 7) * 4];
    float4 ad4 = *(const float4*)&aw[32 + (tx & 7) * 4];
    int h = tx >> 3;

    #pragma unroll
    for (int i = 0; i < 8; i++) {
        int row = row0 + ty * 8 + i;   // warp-uniform
        if (row >= NN) break;
        float4 v = make_float4(acc[i][0], acc[i][1], acc[i][2], acc[i][3]);
        *(float4*)&g_Wx[row * MOUT + tx * 4] = v;

        float ps = v.x * as4.x + v.y * as4.y + v.z * as4.z + v.w * as4.w;
        float pd = v.x * ad4.x + v.y * ad4.y + v.z * ad4.z + v.w * ad4.w;
        ps += __shfl_xor_sync(0xffffffffu, ps, 1);
        ps += __shfl_xor_sync(0xffffffffu, ps, 2);
        ps += __shfl_xor_sync(0xffffffffu, ps, 4);
        pd += __shfl_xor_sync(0xffffffffu, pd, 1);
        pd += __shfl_xor_sync(0xffffffffu, pd, 2);
        pd += __shfl_xor_sync(0xffffffffu, pd, 4);
        if ((tx & 7) == 0) {
            g_ssrc[row * NH + h] = ps;
            g_sdst[row * NH + h] = pd;
        }
    }
}

// ---------------------------------------------------------------------------
// Kernel 2: per-edge softmax numerator + denom scatter
// ---------------------------------------------------------------------------
__device__ __forceinline__ float lrelu_exp(float v) {
    float r = v > 0.f ? v : 0.2f * v;
    return __expf(r);
}

__global__ void edge_score_kernel(const int* __restrict__ ei) {
    int e = blockIdx.x * blockDim.x + threadIdx.x;
    if (e >= NE) return;
    int s = ei[e];
    int d = ei[NE + e];
    float4 a = *(const float4*)&g_ssrc[s * 4];
    float4 b = *(const float4*)&g_sdst[d * 4];
    float4 r;
    r.x = lrelu_exp(a.x + b.x);
    r.y = lrelu_exp(a.y + b.y);
    r.z = lrelu_exp(a.z + b.z);
    r.w = lrelu_exp(a.w + b.w);
    *(float4*)&g_eexp[e * 4] = r;
    red_add_v4(&g_denom[d * 4], r);
}

// ---------------------------------------------------------------------------
// Kernel 3: edge aggregation. One warp per edge; lane covers 4 output cols.
// ---------------------------------------------------------------------------
__global__ __launch_bounds__(256)
void edge_agg_kernel(const int* __restrict__ ei) {
    int lane = threadIdx.x & 31;
    int e = (blockIdx.x * blockDim.x + threadIdx.x) >> 5;
    if (e >= NE) return;
    int s = ei[e];
    int d = ei[NE + e];
    float4 ee = *(const float4*)&g_eexp[e * 4];
    float4 dn = *(const float4*)&g_denom[d * 4];
    float a0 = __fdividef(ee.x, dn.x + 1e-8f);
    float a1 = __fdividef(ee.y, dn.y + 1e-8f);
    float a2 = __fdividef(ee.z, dn.z + 1e-8f);
    float a3 = __fdividef(ee.w, dn.w + 1e-8f);
    int h = lane >> 3;
    float al = (h == 0) ? a0 : (h == 1) ? a1 : (h == 2) ? a2 : a3;
    float4 w = *(const float4*)&g_Wx[s * MOUT + lane * 4];
    w.x *= al; w.y *= al; w.z *= al; w.w *= al;
    red_add_v4(&g_accum[d * MOUT + lane * 4], w);
}

// ---------------------------------------------------------------------------
// Kernel 4: ELU epilogue -> d_out
// ---------------------------------------------------------------------------
__global__ void elu_kernel(float* __restrict__ out) {
    int i = blockIdx.x * blockDim.x + threadIdx.x;
    if (i >= NN * MOUT / 4) return;
    float4 v = ((float4*)g_accum)[i];
    v.x = v.x > 0.f ? v.x : expm1f(v.x);
    v.y = v.y > 0.f ? v.y : expm1f(v.y);
    v.z = v.z > 0.f ? v.z : expm1f(v.z);
    v.w = v.w > 0.f ? v.w : expm1f(v.w);
    ((float4*)out)[i] = v;
}

// ---------------------------------------------------------------------------
extern "C" void kernel_launch(void* const* d_in, const int* in_sizes, int n_in,
                              void* d_out, int out_size) {
    const float* x  = (const float*)d_in[0];
    const int*   ei = (const int*)d_in[1];
    const float* W  = (const float*)d_in[2];
    const float* aw = (const float*)d_in[3];
    float* out = (float*)d_out;

    zero_kernel<<<(NN * MOUT / 4 + 255) / 256, 256>>>();
    gemm_score_kernel<<<(NN + BM - 1) / BM, 256>>>(x, W, aw);
    edge_score_kernel<<<(NE + 255) / 256, 256>>>(ei);
    edge_agg_kernel<<<NE * 32 / 256, 256>>>(ei);
    elu_kernel<<<(NN * MOUT / 4 + 255) / 256, 256>>>(out);
}

// round 2
// speedup vs baseline: 1.3662x; 1.3662x over previous
#include <cuda_runtime.h>

#define NN   50000
#define NE   800000
#define KIN  256
#define MOUT 128
#define NH   4
#define NB   196        // ceil(NN/256)

// Scratch (allocation-free rule: __device__ globals)
__device__ __align__(16) float g_Wx[NN * MOUT];     // 25.6 MB
__device__ __align__(16) float g_ssrc[NN * NH];     // 0.8 MB
__device__ __align__(16) float g_sdst[NN * NH];     // 0.8 MB
__device__ int g_cnt[NN];
__device__ int g_scan[NN];
__device__ int g_bsum[256];
__device__ int g_off[NN + 1];
__device__ int g_cur[NN];
__device__ int g_esrc[NE];                          // src ids sorted by dst

// ---------------------------------------------------------------------------
// CSR build: zero -> histogram -> 2-level scan -> fill
// ---------------------------------------------------------------------------
__global__ void zero_cnt_kernel() {
    int i = blockIdx.x * blockDim.x + threadIdx.x;
    if (i < NN) g_cnt[i] = 0;
}

__global__ void hist_kernel(const int* __restrict__ ei) {
    int e = blockIdx.x * blockDim.x + threadIdx.x;
    if (e < NE) atomicAdd(&g_cnt[ei[NE + e]], 1);
}

__global__ void scan1_kernel() {   // per-block inclusive scan + block sums
    __shared__ int sh[256];
    int t = threadIdx.x;
    int i = blockIdx.x * 256 + t;
    int v = (i < NN) ? g_cnt[i] : 0;
    sh[t] = v;
    __syncthreads();
    #pragma unroll
    for (int ofs = 1; ofs < 256; ofs <<= 1) {
        int add = (t >= ofs) ? sh[t - ofs] : 0;
        __syncthreads();
        sh[t] += add;
        __syncthreads();
    }
    if (i < NN) g_scan[i] = sh[t];
    if (t == 255) g_bsum[blockIdx.x] = sh[255];
}

__global__ void scan2_kernel() {   // single-block exclusive scan of block sums
    __shared__ int sh[256];
    int t = threadIdx.x;
    int v = (t < NB) ? g_bsum[t] : 0;
    sh[t] = v;
    __syncthreads();
    #pragma unroll
    for (int ofs = 1; ofs < 256; ofs <<= 1) {
        int add = (t >= ofs) ? sh[t - ofs] : 0;
        __syncthreads();
        sh[t] += add;
        __syncthreads();
    }
    g_bsum[t] = sh[t] - v;   // exclusive
}

__global__ void scan3_kernel() {   // final exclusive offsets + cursor reset
    int i = blockIdx.x * blockDim.x + threadIdx.x;
    if (i < NN) {
        g_off[i] = g_scan[i] - g_cnt[i] + g_bsum[i >> 8];
        g_cur[i] = 0;
    }
    if (i == 0) g_off[NN] = NE;
}

__global__ void fill_kernel(const int* __restrict__ ei) {
    int e = blockIdx.x * blockDim.x + threadIdx.x;
    if (e >= NE) return;
    int s = ei[e];
    int d = ei[NE + e];
    int pos = g_off[d] + atomicAdd(&g_cur[d], 1);
    g_esrc[pos] = s;
}

// ---------------------------------------------------------------------------
// GEMM Wx = x @ W^T (fp32 tiled) + fused per-head score epilogue
// ---------------------------------------------------------------------------
#define BM 64
#define BK 16

__global__ __launch_bounds__(256)
void gemm_score_kernel(const float* __restrict__ x,
                       const float* __restrict__ W,
                       const float* __restrict__ aw) {
    __shared__ float Xs[BK][BM];
    __shared__ float Ws[BK][MOUT];

    int tid = threadIdx.x;
    int tx  = tid & 31;
    int ty  = tid >> 5;
    int row0 = blockIdx.x * BM;

    float acc[8][4];
    #pragma unroll
    for (int i = 0; i < 8; i++)
        #pragma unroll
        for (int j = 0; j < 4; j++) acc[i][j] = 0.f;

    for (int k0 = 0; k0 < KIN; k0 += BK) {
        {
            int m  = tid >> 2;
            int kv = (tid & 3) * 4;
            int row = row0 + m;
            float4 v = make_float4(0.f, 0.f, 0.f, 0.f);
            if (row < NN) v = *(const float4*)&x[row * KIN + k0 + kv];
            Xs[kv + 0][m] = v.x; Xs[kv + 1][m] = v.y;
            Xs[kv + 2][m] = v.z; Xs[kv + 3][m] = v.w;
        }
        #pragma unroll
        for (int j = 0; j < 2; j++) {
            int idx = tid * 2 + j;
            int o   = idx >> 2;
            int kv  = (idx & 3) * 4;
            float4 v = *(const float4*)&W[o * KIN + k0 + kv];
            Ws[kv + 0][o] = v.x; Ws[kv + 1][o] = v.y;
            Ws[kv + 2][o] = v.z; Ws[kv + 3][o] = v.w;
        }
        __syncthreads();

        #pragma unroll
        for (int k = 0; k < BK; k++) {
            float4 b = *(float4*)&Ws[k][tx * 4];
            #pragma unroll
            for (int i = 0; i < 8; i++) {
                float a = Xs[k][ty * 8 + i];
                acc[i][0] += a * b.x; acc[i][1] += a * b.y;
                acc[i][2] += a * b.z; acc[i][3] += a * b.w;
            }
        }
        __syncthreads();
    }

    float4 as4 = *(const float4*)&aw[(tx & 7) * 4];
    float4 ad4 = *(const float4*)&aw[32 + (tx & 7) * 4];
    int h = tx >> 3;

    #pragma unroll
    for (int i = 0; i < 8; i++) {
        int row = row0 + ty * 8 + i;
        if (row >= NN) break;
        float4 v = make_float4(acc[i][0], acc[i][1], acc[i][2], acc[i][3]);
        *(float4*)&g_Wx[row * MOUT + tx * 4] = v;

        float ps = v.x * as4.x + v.y * as4.y + v.z * as4.z + v.w * as4.w;
        float pd = v.x * ad4.x + v.y * ad4.y + v.z * ad4.z + v.w * ad4.w;
        ps += __shfl_xor_sync(0xffffffffu, ps, 1);
        ps += __shfl_xor_sync(0xffffffffu, ps, 2);
        ps += __shfl_xor_sync(0xffffffffu, ps, 4);
        pd += __shfl_xor_sync(0xffffffffu, pd, 1);
        pd += __shfl_xor_sync(0xffffffffu, pd, 2);
        pd += __shfl_xor_sync(0xffffffffu, pd, 4);
        if ((tx & 7) == 0) {
            g_ssrc[row * NH + h] = ps;
            g_sdst[row * NH + h] = pd;
        }
    }
}

// ---------------------------------------------------------------------------
// Aggregation: one warp per destination node, gather-only, fused ELU.
// ---------------------------------------------------------------------------
__device__ __forceinline__ float lrelu_exp(float v) {
    float r = v > 0.f ? v : 0.2f * v;
    return __expf(r);
}

__global__ __launch_bounds__(256)
void agg_kernel(float* __restrict__ out) {
    int d = blockIdx.x * 8 + (threadIdx.x >> 5);
    if (d >= NN) return;
    int lane = threadIdx.x & 31;
    int beg = g_off[d];
    int end = g_off[d + 1];

    float4 sd4 = *(const float4*)&g_sdst[d * 4];

    // Pass 1: denom (lane-strided over edges, warp-reduced)
    float4 dn = make_float4(0.f, 0.f, 0.f, 0.f);
    for (int j = beg + lane; j < end; j += 32) {
        int s = g_esrc[j];
        float4 a = *(const float4*)&g_ssrc[s * 4];
        dn.x += lrelu_exp(a.x + sd4.x);
        dn.y += lrelu_exp(a.y + sd4.y);
        dn.z += lrelu_exp(a.z + sd4.z);
        dn.w += lrelu_exp(a.w + sd4.w);
    }
    #pragma unroll
    for (int m = 16; m; m >>= 1) {
        dn.x += __shfl_xor_sync(0xffffffffu, dn.x, m);
        dn.y += __shfl_xor_sync(0xffffffffu, dn.y, m);
        dn.z += __shfl_xor_sync(0xffffffffu, dn.z, m);
        dn.w += __shfl_xor_sync(0xffffffffu, dn.w, m);
    }

    int h = lane >> 3;
    float dnh = (h == 0) ? dn.x : (h == 1) ? dn.y : (h == 2) ? dn.z : dn.w;
    float adh = (h == 0) ? sd4.x : (h == 1) ? sd4.y : (h == 2) ? sd4.z : sd4.w;
    float invd = __fdividef(1.f, dnh + 1e-8f);

    // Pass 2: weighted gather of Wx[src] (serial over edges, lane = 4 cols)
    float4 acc = make_float4(0.f, 0.f, 0.f, 0.f);
    #pragma unroll 2
    for (int j = beg; j < end; j++) {
        int s = g_esrc[j];                               // warp-uniform
        float al = lrelu_exp(g_ssrc[s * 4 + h] + adh) * invd;
        float4 w = *(const float4*)&g_Wx[s * MOUT + lane * 4];
        acc.x += al * w.x; acc.y += al * w.y;
        acc.z += al * w.z; acc.w += al * w.w;
    }

    acc.x = acc.x > 0.f ? acc.x : expm1f(acc.x);
    acc.y = acc.y > 0.f ? acc.y : expm1f(acc.y);
    acc.z = acc.z > 0.f ? acc.z : expm1f(acc.z);
    acc.w = acc.w > 0.f ? acc.w : expm1f(acc.w);
    *(float4*)&out[d * MOUT + lane * 4] = acc;
}

// ---------------------------------------------------------------------------
extern "C" void kernel_launch(void* const* d_in, const int* in_sizes, int n_in,
                              void* d_out, int out_size) {
    const float* x  = (const float*)d_in[0];
    const int*   ei = (const int*)d_in[1];
    const float* W  = (const float*)d_in[2];
    const float* aw = (const float*)d_in[3];
    float* out = (float*)d_out;

    zero_cnt_kernel<<<NB, 256>>>();
    gemm_score_kernel<<<(NN + BM - 1) / BM, 256>>>(x, W, aw);
    hist_kernel<<<(NE + 255) / 256, 256>>>(ei);
    scan1_kernel<<<NB, 256>>>();
    scan2_kernel<<<1, 256>>>();
    scan3_kernel<<<NB, 256>>>();
    fill_kernel<<<(NE + 255) / 256, 256>>>(ei);
    agg_kernel<<<(NN + 7) / 8, 256>>>(out);
}